// round 7
// baseline (speedup 1.0000x reference)
#include <cuda_runtime.h>

// Encoder: out[b,e] = relu( sum_i combined[b,i] * weight[b,i,e] )
// combined = [ features[nodes[b]] , mean_j features[neigh_idx[b,j]] ]  (256 dims)
// Shapes: features [100000,128] f32, weight [4096,256,128] f32,
//         nodes [4096] i32, neigh_idx [4096,10] i32, out [4096,128] f32.
//
// DRAM-bound streaming kernel (~533MB compulsory, at ~81% of HBM spec).
// This revision streams weight with native 256-bit loads (LDG.256 via
// ld.global.nc.L2::evict_first.v8.b32): 1024B per warp request, half the
// instructions/wavefronts per byte, evict-first keeps L2 clean for gathers.
//  - lanes 0..15 cover row k, lanes 16..31 row k+1; parity folded by shfl.
//  - warp-local gather phase (no pre-stream block barrier), occ 10 CTAs/SM.

#define FEAT 128
#define EMBED 128
#define TWO_FEAT 256
#define NUM_SAMPLE 10

struct F8 { float v0,v1,v2,v3,v4,v5,v6,v7; };

__device__ __forceinline__ F8 ldg256_stream(const float* p) {
    F8 r;
    asm("ld.global.nc.L2::evict_first.v8.b32 {%0,%1,%2,%3,%4,%5,%6,%7}, [%8];"
        : "=f"(r.v0), "=f"(r.v1), "=f"(r.v2), "=f"(r.v3),
          "=f"(r.v4), "=f"(r.v5), "=f"(r.v6), "=f"(r.v7)
        : "l"(p));
    return r;
}

__global__ __launch_bounds__(128, 10)
void encoder_kernel(const float* __restrict__ features,
                    const float* __restrict__ weight,
                    const int*   __restrict__ nodes,
                    const int*   __restrict__ neigh,
                    float*       __restrict__ out)
{
    __shared__ float comb[TWO_FEAT];
    __shared__ float part[4][EMBED];

    const int b = blockIdx.x;
    const int t = threadIdx.x;          // 0..127
    const int warp = t >> 5;
    const int lane = t & 31;

    // ---- Phase 1 (warp-local): warp w builds comb[64w .. 64w+64).
    //   warp 0 -> self dims [0,64)     warp 1 -> self dims [64,128)
    //   warp 2 -> mean dims [0,64)     warp 3 -> mean dims [64,128)
    {
        const int dim0 = (warp & 1) * 64 + lane * 2;
        float2 v;
        if (warp < 2) {
            const int node = __ldg(&nodes[b]);
            v = *reinterpret_cast<const float2*>(&features[(size_t)node * FEAT + dim0]);
        } else {
            float sx = 0.0f, sy = 0.0f;
            #pragma unroll
            for (int j = 0; j < NUM_SAMPLE; ++j) {
                const int nb = __ldg(&neigh[b * NUM_SAMPLE + j]);
                const float2 f = *reinterpret_cast<const float2*>(
                    &features[(size_t)nb * FEAT + dim0]);
                sx += f.x; sy += f.y;
            }
            v.x = sx * (1.0f / NUM_SAMPLE);
            v.y = sy * (1.0f / NUM_SAMPLE);
        }
        *reinterpret_cast<float2*>(&comb[warp * 64 + lane * 2]) = v;
        __syncwarp();
    }

    // ---- Phase 2: per-sample matvec, streaming weight[b] (128 KB/CTA).
    // warp w handles rows [w*64, w*64+64) == the comb slice it wrote.
    // Per k-step the warp covers two full rows (1024B) with two LDG.256:
    // lane half (lane>>4) selects row parity, (lane&15)*8 selects e-offset.
    const float* __restrict__ Wbase =
        weight + (size_t)b * TWO_FEAT * EMBED;
    const int i0 = warp * 64;
    const int eo = (lane & 15) * 8;     // e offset within the row
    const int par = lane >> 4;          // row parity this half-warp covers

    float a0=0.f,a1=0.f,a2=0.f,a3=0.f,a4=0.f,a5=0.f,a6=0.f,a7=0.f;

    #pragma unroll 4
    for (int k = 0; k < 64; k += 2) {
        const int row = i0 + k + par;
        const float c = comb[row];
        const F8 w = ldg256_stream(Wbase + (size_t)row * EMBED + eo);
        a0 = fmaf(c, w.v0, a0); a1 = fmaf(c, w.v1, a1);
        a2 = fmaf(c, w.v2, a2); a3 = fmaf(c, w.v3, a3);
        a4 = fmaf(c, w.v4, a4); a5 = fmaf(c, w.v5, a5);
        a6 = fmaf(c, w.v6, a6); a7 = fmaf(c, w.v7, a7);
    }

    // fold the two row-parities: lane i (+) lane i+16 hold the same e-range
    a0 += __shfl_xor_sync(0xffffffffu, a0, 16);
    a1 += __shfl_xor_sync(0xffffffffu, a1, 16);
    a2 += __shfl_xor_sync(0xffffffffu, a2, 16);
    a3 += __shfl_xor_sync(0xffffffffu, a3, 16);
    a4 += __shfl_xor_sync(0xffffffffu, a4, 16);
    a5 += __shfl_xor_sync(0xffffffffu, a5, 16);
    a6 += __shfl_xor_sync(0xffffffffu, a6, 16);
    a7 += __shfl_xor_sync(0xffffffffu, a7, 16);

    if (lane < 16) {
        float4* dst = reinterpret_cast<float4*>(&part[warp][eo]);
        dst[0] = make_float4(a0, a1, a2, a3);
        dst[1] = make_float4(a4, a5, a6, a7);
    }
    __syncthreads();

    // ---- reduce 4 warps, relu, store (coalesced 512B)
    const float v = part[0][t] + part[1][t] + part[2][t] + part[3][t];
    out[(size_t)b * EMBED + t] = fmaxf(v, 0.0f);
}

extern "C" void kernel_launch(void* const* d_in, const int* in_sizes, int n_in,
                              void* d_out, int out_size)
{
    const float* features = (const float*)d_in[0];
    const float* weight   = (const float*)d_in[1];
    const int*   nodes    = (const int*)d_in[2];
    const int*   neigh    = (const int*)d_in[3];
    float*       out      = (float*)d_out;

    const int batch = in_sizes[2];      // 4096 (nodes element count)
    encoder_kernel<<<batch, 128>>>(features, weight, nodes, neigh, out);
}

// round 8
// speedup vs baseline: 1.0030x; 1.0030x over previous
#include <cuda_runtime.h>

// Encoder: out[b,e] = relu( sum_i combined[b,i] * weight[b,i,e] )
// combined = [ features[nodes[b]] , mean_j features[neigh_idx[b,j]] ]  (256 dims)
// Shapes: features [100000,128] f32, weight [4096,256,128] f32,
//         nodes [4096] i32, neigh_idx [4096,10] i32, out [4096,128] f32.
//
// DRAM-bound streaming kernel (~533MB compulsory, at ~81% of HBM spec).
// This revision streams weight with native 256-bit loads (LDG.256 via
// ld.global.nc.L2::evict_first.v8.b32): 1024B per warp request, half the
// instructions/wavefronts per byte, evict-first keeps L2 clean for gathers.
//  - lanes 0..15 cover row k, lanes 16..31 row k+1; parity folded by shfl.
//  - warp-local gather phase (no pre-stream block barrier), occ 10 CTAs/SM.

#define FEAT 128
#define EMBED 128
#define TWO_FEAT 256
#define NUM_SAMPLE 10

struct F8 { float v0,v1,v2,v3,v4,v5,v6,v7; };

__device__ __forceinline__ F8 ldg256_stream(const float* p) {
    F8 r;
    asm("ld.global.nc.L2::evict_first.v8.b32 {%0,%1,%2,%3,%4,%5,%6,%7}, [%8];"
        : "=f"(r.v0), "=f"(r.v1), "=f"(r.v2), "=f"(r.v3),
          "=f"(r.v4), "=f"(r.v5), "=f"(r.v6), "=f"(r.v7)
        : "l"(p));
    return r;
}

__global__ __launch_bounds__(128, 10)
void encoder_kernel(const float* __restrict__ features,
                    const float* __restrict__ weight,
                    const int*   __restrict__ nodes,
                    const int*   __restrict__ neigh,
                    float*       __restrict__ out)
{
    __shared__ float comb[TWO_FEAT];
    __shared__ float part[4][EMBED];

    const int b = blockIdx.x;
    const int t = threadIdx.x;          // 0..127
    const int warp = t >> 5;
    const int lane = t & 31;

    // ---- Phase 1 (warp-local): warp w builds comb[64w .. 64w+64).
    //   warp 0 -> self dims [0,64)     warp 1 -> self dims [64,128)
    //   warp 2 -> mean dims [0,64)     warp 3 -> mean dims [64,128)
    {
        const int dim0 = (warp & 1) * 64 + lane * 2;
        float2 v;
        if (warp < 2) {
            const int node = __ldg(&nodes[b]);
            v = *reinterpret_cast<const float2*>(&features[(size_t)node * FEAT + dim0]);
        } else {
            float sx = 0.0f, sy = 0.0f;
            #pragma unroll
            for (int j = 0; j < NUM_SAMPLE; ++j) {
                const int nb = __ldg(&neigh[b * NUM_SAMPLE + j]);
                const float2 f = *reinterpret_cast<const float2*>(
                    &features[(size_t)nb * FEAT + dim0]);
                sx += f.x; sy += f.y;
            }
            v.x = sx * (1.0f / NUM_SAMPLE);
            v.y = sy * (1.0f / NUM_SAMPLE);
        }
        *reinterpret_cast<float2*>(&comb[warp * 64 + lane * 2]) = v;
        __syncwarp();
    }

    // ---- Phase 2: per-sample matvec, streaming weight[b] (128 KB/CTA).
    // warp w handles rows [w*64, w*64+64) == the comb slice it wrote.
    // Per k-step the warp covers two full rows (1024B) with two LDG.256:
    // lane half (lane>>4) selects row parity, (lane&15)*8 selects e-offset.
    const float* __restrict__ Wbase =
        weight + (size_t)b * TWO_FEAT * EMBED;
    const int i0 = warp * 64;
    const int eo = (lane & 15) * 8;     // e offset within the row
    const int par = lane >> 4;          // row parity this half-warp covers

    float a0=0.f,a1=0.f,a2=0.f,a3=0.f,a4=0.f,a5=0.f,a6=0.f,a7=0.f;

    #pragma unroll 4
    for (int k = 0; k < 64; k += 2) {
        const int row = i0 + k + par;
        const float c = comb[row];
        const F8 w = ldg256_stream(Wbase + (size_t)row * EMBED + eo);
        a0 = fmaf(c, w.v0, a0); a1 = fmaf(c, w.v1, a1);
        a2 = fmaf(c, w.v2, a2); a3 = fmaf(c, w.v3, a3);
        a4 = fmaf(c, w.v4, a4); a5 = fmaf(c, w.v5, a5);
        a6 = fmaf(c, w.v6, a6); a7 = fmaf(c, w.v7, a7);
    }

    // fold the two row-parities: lane i (+) lane i+16 hold the same e-range
    a0 += __shfl_xor_sync(0xffffffffu, a0, 16);
    a1 += __shfl_xor_sync(0xffffffffu, a1, 16);
    a2 += __shfl_xor_sync(0xffffffffu, a2, 16);
    a3 += __shfl_xor_sync(0xffffffffu, a3, 16);
    a4 += __shfl_xor_sync(0xffffffffu, a4, 16);
    a5 += __shfl_xor_sync(0xffffffffu, a5, 16);
    a6 += __shfl_xor_sync(0xffffffffu, a6, 16);
    a7 += __shfl_xor_sync(0xffffffffu, a7, 16);

    if (lane < 16) {
        float4* dst = reinterpret_cast<float4*>(&part[warp][eo]);
        dst[0] = make_float4(a0, a1, a2, a3);
        dst[1] = make_float4(a4, a5, a6, a7);
    }
    __syncthreads();

    // ---- reduce 4 warps, relu, store (coalesced 512B)
    const float v = part[0][t] + part[1][t] + part[2][t] + part[3][t];
    out[(size_t)b * EMBED + t] = fmaxf(v, 0.0f);
}

extern "C" void kernel_launch(void* const* d_in, const int* in_sizes, int n_in,
                              void* d_out, int out_size)
{
    const float* features = (const float*)d_in[0];
    const float* weight   = (const float*)d_in[1];
    const int*   nodes    = (const int*)d_in[2];
    const int*   neigh    = (const int*)d_in[3];
    float*       out      = (float*)d_out;

    const int batch = in_sizes[2];      // 4096 (nodes element count)
    encoder_kernel<<<batch, 128>>>(features, weight, nodes, neigh, out);
}